// round 10
// baseline (speedup 1.0000x reference)
#include <cuda_runtime.h>
#include <cuda_bf16.h>

#define OUT_UNITS 128
#define WARPS_PER_BLOCK 4
#define WIN 32                       // nnz per warp window

// ---------------------------------------------------------------------------
// Dtype probe: rows sorted ascending over [0, 16384). If int64 (LE), every odd
// 32-bit word is a zero high-half. If int32, odd words near n/4, n/2, 3n/4 are
// sorted row ids ~4096/8192/12288. Probed indices odd and < n: safe for both.
// ---------------------------------------------------------------------------
__device__ __forceinline__ int probe_is64(const int* __restrict__ rows32, int n) {
    int j1 = (n / 2) | 1;
    int j2 = (n / 4) | 1;
    int j3 = (int)(((long long)3 * n) / 4) | 1;
    int s = rows32[j1] | rows32[j2] | rows32[j3];
    return (s == 0) ? 1 : 0;
}

// ---------------------------------------------------------------------------
// SpMM, nnz-balanced: each warp owns exactly WIN consecutive nnz. Rows are
// sorted, so a window holds ~1-2 row segments. Boundaries found with one
// ballot; per segment the proven R2 gather loop runs (batches of 4
// independent LDG.128, 16 L2 sectors in flight), then the accumulator is
// flushed with 4 RED.F32 atomics. Perfect work balance, no offsets pass.
// ---------------------------------------------------------------------------
__global__ void __launch_bounds__(32 * WARPS_PER_BLOCK)
spmm_kernel(const float* __restrict__ values,
            const float* __restrict__ w,
            const int*   __restrict__ rows32,
            const int*   __restrict__ cols32,
            float*       __restrict__ out,
            int nnz) {
    const int warp  = threadIdx.x >> 5;
    const int lane  = threadIdx.x & 31;
    const int gwarp = blockIdx.x * WARPS_PER_BLOCK + warp;
    const int k0    = gwarp * WIN;
    if (k0 >= nnz) return;

    const int is64 = probe_is64(rows32, nnz);

    __shared__ float2 stage[WARPS_PER_BLOCK][WIN];   // (value, col bits)
    __shared__ int    srow[WARPS_PER_BLOCK][WIN];

    // Stage this window's (v, c, r); find row-boundary mask via ballot.
    const int  k     = k0 + lane;
    const bool valid = (k < nnz);
    float v = 0.0f; int c = 0; int r = 0; int prev = -1;
    if (valid) {
        v = values[k];
        if (is64) {
            c = cols32[2 * k];
            r = rows32[2 * k];
            if (k > 0) prev = rows32[2 * (k - 1)];
        } else {
            c = cols32[k];
            r = rows32[k];
            if (k > 0) prev = rows32[k - 1];
        }
    }
    stage[warp][lane] = make_float2(v, __int_as_float(c));
    srow[warp][lane]  = r;

    const unsigned vmask = __ballot_sync(0xffffffffu, valid);
    const int      m     = __popc(vmask);                       // valid count
    unsigned bmask = (__ballot_sync(0xffffffffu, valid && (r != prev)) | 1u)
                     & vmask;
    __syncwarp();

    const float4* __restrict__ w4 = (const float4*)w;           // w4[c*32 + lane]

    // Segment loop (bmask is warp-uniform: no divergence).
    while (bmask) {
        const int s = __ffs(bmask) - 1;
        bmask &= bmask - 1;
        const int e  = bmask ? (__ffs(bmask) - 1) : m;
        const int rs = srow[warp][s];

        float4 acc = make_float4(0.f, 0.f, 0.f, 0.f);

        int i = s;
        #pragma unroll 1
        for (; i + 4 <= e; i += 4) {
            const float2 p0 = stage[warp][i + 0];
            const float2 p1 = stage[warp][i + 1];
            const float2 p2 = stage[warp][i + 2];
            const float2 p3 = stage[warp][i + 3];
            // 4 independent coalesced LDG.128s in flight
            const float4 w0 = w4[(size_t)__float_as_int(p0.y) * 32 + lane];
            const float4 w1 = w4[(size_t)__float_as_int(p1.y) * 32 + lane];
            const float4 w2 = w4[(size_t)__float_as_int(p2.y) * 32 + lane];
            const float4 w3 = w4[(size_t)__float_as_int(p3.y) * 32 + lane];
            acc.x = fmaf(p0.x, w0.x, acc.x); acc.y = fmaf(p0.x, w0.y, acc.y);
            acc.z = fmaf(p0.x, w0.z, acc.z); acc.w = fmaf(p0.x, w0.w, acc.w);
            acc.x = fmaf(p1.x, w1.x, acc.x); acc.y = fmaf(p1.x, w1.y, acc.y);
            acc.z = fmaf(p1.x, w1.z, acc.z); acc.w = fmaf(p1.x, w1.w, acc.w);
            acc.x = fmaf(p2.x, w2.x, acc.x); acc.y = fmaf(p2.x, w2.y, acc.y);
            acc.z = fmaf(p2.x, w2.z, acc.z); acc.w = fmaf(p2.x, w2.w, acc.w);
            acc.x = fmaf(p3.x, w3.x, acc.x); acc.y = fmaf(p3.x, w3.y, acc.y);
            acc.z = fmaf(p3.x, w3.z, acc.z); acc.w = fmaf(p3.x, w3.w, acc.w);
        }
        for (; i < e; i++) {
            const float2 p = stage[warp][i];
            const float4 wv = w4[(size_t)__float_as_int(p.y) * 32 + lane];
            acc.x = fmaf(p.x, wv.x, acc.x); acc.y = fmaf(p.x, wv.y, acc.y);
            acc.z = fmaf(p.x, wv.z, acc.z); acc.w = fmaf(p.x, wv.w, acc.w);
        }

        // Flush segment: 4 RED.F32 per lane (return value unused -> RED).
        float* o = out + (size_t)rs * OUT_UNITS + lane * 4;
        atomicAdd(o + 0, acc.x);
        atomicAdd(o + 1, acc.y);
        atomicAdd(o + 2, acc.z);
        atomicAdd(o + 3, acc.w);
    }
}

// ---------------------------------------------------------------------------
// Launch — memset + single balanced kernel.
// Inputs (metadata order): values f32[NNZ], w f32[8192*128],
//                          rows int{32,64}[NNZ], cols int{32,64}[NNZ], n_rows
// ---------------------------------------------------------------------------
extern "C" void kernel_launch(void* const* d_in, const int* in_sizes, int n_in,
                              void* d_out, int out_size) {
    const float* values = (const float*)d_in[0];
    const float* w      = (const float*)d_in[1];
    const int*   rows32 = (const int*)d_in[2];
    const int*   cols32 = (const int*)d_in[3];
    float*       out    = (float*)d_out;

    const int nnz = in_sizes[0];

    // out accumulates via RED: zero-init first (async, graph-capturable).
    cudaMemsetAsync(out, 0, (size_t)out_size * sizeof(float));

    const int total_warps = (nnz + WIN - 1) / WIN;
    const int blocks      = (total_warps + WARPS_PER_BLOCK - 1) / WARPS_PER_BLOCK;
    spmm_kernel<<<blocks, 32 * WARPS_PER_BLOCK>>>(values, w, rows32, cols32, out, nnz);
}

// round 11
// speedup vs baseline: 1.0676x; 1.0676x over previous
#include <cuda_runtime.h>
#include <cuda_bf16.h>

#define OUT_UNITS 128
#define MAX_ROWS  16384
#define WARPS_PER_BLOCK 2
#define ELEMS_PER_THREAD 8

// ---------------------------------------------------------------------------
// Scratch (device globals — no allocation allowed in kernel_launch)
// ---------------------------------------------------------------------------
__device__ int g_is64;                       // 1 if rows/cols are int64, 0 if int32
__device__ int g_row_start[MAX_ROWS + 1];    // CSR-style row offsets

// ---------------------------------------------------------------------------
// Dtype probe: rows sorted ascending over [0, 16384). If int64 (LE), every odd
// 32-bit word is a zero high-half. If int32, odd words near n/4, n/2, 3n/4 are
// sorted row ids ~4096/8192/12288. Probed indices odd and < n: safe for both.
// ---------------------------------------------------------------------------
__device__ __forceinline__ int probe_is64(const int* __restrict__ rows32, int n) {
    int j1 = (n / 2) | 1;
    int j2 = (n / 4) | 1;
    int j3 = (int)(((long long)3 * n) / 4) | 1;
    int s = rows32[j1] | rows32[j2] | rows32[j3];
    return (s == 0) ? 1 : 0;
}

// ---------------------------------------------------------------------------
// Kernel 1: build row offsets from sorted COO rows (fused dtype detection).
// 8 elements per thread, vectorized int4 loads.
// ---------------------------------------------------------------------------
__global__ void build_offsets_kernel(const int* __restrict__ rows32, int nnz, int n_rows) {
    const int is64 = probe_is64(rows32, nnz);

    const int t  = blockIdx.x * blockDim.x + threadIdx.x;
    if (t == 0) g_is64 = is64;
    const int k0 = t * ELEMS_PER_THREAD;
    if (k0 >= nnz) return;

    const int cnt = min(ELEMS_PER_THREAD, nnz - k0);
    int r[ELEMS_PER_THREAD];
    if (is64) {
        if (cnt == ELEMS_PER_THREAD) {
            #pragma unroll
            for (int q = 0; q < 4; q++) {
                const int4 a = ((const int4*)rows32)[k0 / 2 + q];
                r[2 * q]     = a.x;
                r[2 * q + 1] = a.z;
            }
        } else {
            for (int j = 0; j < cnt; j++) r[j] = rows32[2 * (k0 + j)];
        }
    } else {
        if (cnt == ELEMS_PER_THREAD) {
            const int4 a = ((const int4*)rows32)[k0 / 4];
            const int4 b = ((const int4*)rows32)[k0 / 4 + 1];
            r[0] = a.x; r[1] = a.y; r[2] = a.z; r[3] = a.w;
            r[4] = b.x; r[5] = b.y; r[6] = b.z; r[7] = b.w;
        } else {
            for (int j = 0; j < cnt; j++) r[j] = rows32[k0 + j];
        }
    }

    int rp = (k0 == 0) ? -1 : (is64 ? rows32[2 * (k0 - 1)] : rows32[k0 - 1]);
    for (int j = 0; j < cnt; j++) {
        const int rj = r[j];
        for (int x = rp + 1; x <= rj; x++) g_row_start[x] = k0 + j;
        rp = rj;
    }
    if (k0 + cnt == nnz) {
        for (int x = rp + 1; x <= n_rows; x++) g_row_start[x] = nnz;
    }
}

// ---------------------------------------------------------------------------
// Kernel 2: main SpMM — proven R2/R9 inner loop, in 2-warp CTAs for finer
// wave-level load balancing over the Poisson row-length spread.
// One WARP per output row; lane t owns output columns [4t, 4t+4) via float4.
// Stage 32 (val, col) pairs per warp in smem (broadcast LDS reads), gather W
// rows with batches of 4 independent LDG.128 (16 L2 sectors in flight).
// ---------------------------------------------------------------------------
__global__ void __launch_bounds__(32 * WARPS_PER_BLOCK)
spmm_kernel(const float* __restrict__ values,
            const float* __restrict__ w,
            const int*   __restrict__ cols32,
            float*       __restrict__ out) {
    const int warp = threadIdx.x >> 5;
    const int lane = threadIdx.x & 31;
    const int r    = blockIdx.x * WARPS_PER_BLOCK + warp;
    const int is64 = g_is64;

    __shared__ float2 stage[WARPS_PER_BLOCK][32];

    const int lo = g_row_start[r];
    const int hi = g_row_start[r + 1];

    float4 acc = make_float4(0.f, 0.f, 0.f, 0.f);
    const float4* __restrict__ w4 = (const float4*)w;   // w4[c*32 + lane]

    for (int base = lo; base < hi; base += 32) {
        const int m = min(32, hi - base);
        if (lane < m) {
            const int k = base + lane;
            const int c = is64 ? cols32[2 * k] : cols32[k];
            stage[warp][lane] = make_float2(values[k], __int_as_float(c));
        }
        __syncwarp();

        int i = 0;
        #pragma unroll 1
        for (; i + 4 <= m; i += 4) {
            const float2 p0 = stage[warp][i + 0];
            const float2 p1 = stage[warp][i + 1];
            const float2 p2 = stage[warp][i + 2];
            const float2 p3 = stage[warp][i + 3];
            // 4 independent coalesced LDG.128s in flight
            const float4 w0 = w4[(size_t)__float_as_int(p0.y) * 32 + lane];
            const float4 w1 = w4[(size_t)__float_as_int(p1.y) * 32 + lane];
            const float4 w2 = w4[(size_t)__float_as_int(p2.y) * 32 + lane];
            const float4 w3 = w4[(size_t)__float_as_int(p3.y) * 32 + lane];
            acc.x = fmaf(p0.x, w0.x, acc.x); acc.y = fmaf(p0.x, w0.y, acc.y);
            acc.z = fmaf(p0.x, w0.z, acc.z); acc.w = fmaf(p0.x, w0.w, acc.w);
            acc.x = fmaf(p1.x, w1.x, acc.x); acc.y = fmaf(p1.x, w1.y, acc.y);
            acc.z = fmaf(p1.x, w1.z, acc.z); acc.w = fmaf(p1.x, w1.w, acc.w);
            acc.x = fmaf(p2.x, w2.x, acc.x); acc.y = fmaf(p2.x, w2.y, acc.y);
            acc.z = fmaf(p2.x, w2.z, acc.z); acc.w = fmaf(p2.x, w2.w, acc.w);
            acc.x = fmaf(p3.x, w3.x, acc.x); acc.y = fmaf(p3.x, w3.y, acc.y);
            acc.z = fmaf(p3.x, w3.z, acc.z); acc.w = fmaf(p3.x, w3.w, acc.w);
        }
        for (; i < m; i++) {
            const float2 p = stage[warp][i];
            const float4 wv = w4[(size_t)__float_as_int(p.y) * 32 + lane];
            acc.x = fmaf(p.x, wv.x, acc.x); acc.y = fmaf(p.x, wv.y, acc.y);
            acc.z = fmaf(p.x, wv.z, acc.z); acc.w = fmaf(p.x, wv.w, acc.w);
        }
        __syncwarp();
    }

    ((float4*)out)[(size_t)r * 32 + lane] = acc;
}

// ---------------------------------------------------------------------------
// Launch
// Inputs (metadata order): values f32[NNZ], w f32[8192*128],
//                          rows int{32,64}[NNZ], cols int{32,64}[NNZ], n_rows
// ---------------------------------------------------------------------------
extern "C" void kernel_launch(void* const* d_in, const int* in_sizes, int n_in,
                              void* d_out, int out_size) {
    const float* values = (const float*)d_in[0];
    const float* w      = (const float*)d_in[1];
    const int*   rows32 = (const int*)d_in[2];
    const int*   cols32 = (const int*)d_in[3];
    float*       out    = (float*)d_out;

    const int nnz    = in_sizes[0];
    const int n_rows = out_size / OUT_UNITS;

    const int bs = 256;
    const int nthreads = (nnz + ELEMS_PER_THREAD - 1) / ELEMS_PER_THREAD;
    build_offsets_kernel<<<(nthreads + bs - 1) / bs, bs>>>(rows32, nnz, n_rows);

    spmm_kernel<<<n_rows / WARPS_PER_BLOCK, 32 * WARPS_PER_BLOCK>>>(values, w, cols32, out);
}

// round 12
// speedup vs baseline: 1.1060x; 1.0359x over previous
#include <cuda_runtime.h>
#include <cuda_bf16.h>

#define OUT_UNITS 128
#define MAX_ROWS  16384
#define WARPS_PER_BLOCK 2

// ---------------------------------------------------------------------------
// Scratch (device globals — no allocation allowed in kernel_launch)
// ---------------------------------------------------------------------------
__device__ int g_is64;                       // 1 if rows/cols are int64, 0 if int32
__device__ int g_row_start[MAX_ROWS + 1];    // CSR-style row offsets

// ---------------------------------------------------------------------------
// Dtype probe: rows sorted ascending over [0, 16384). If int64 (LE), every odd
// 32-bit word is a zero high-half. If int32, odd words near n/4, n/2, 3n/4 are
// sorted row ids ~4096/8192/12288. Probed indices odd and < n: safe for both.
// ---------------------------------------------------------------------------
__device__ __forceinline__ int probe_is64(const int* __restrict__ rows32, int n) {
    int j1 = (n / 2) | 1;
    int j2 = (n / 4) | 1;
    int j3 = (int)(((long long)3 * n) / 4) | 1;
    int s = rows32[j1] | rows32[j2] | rows32[j3];
    return (s == 0) ? 1 : 0;
}

// ---------------------------------------------------------------------------
// Kernel 1: build row offsets from sorted COO rows (fused dtype detection).
// 4 elements per thread, vectorized int4 loads (R9-proven fastest variant).
// ---------------------------------------------------------------------------
__global__ void build_offsets_kernel(const int* __restrict__ rows32, int nnz, int n_rows) {
    const int is64 = probe_is64(rows32, nnz);

    const int t  = blockIdx.x * blockDim.x + threadIdx.x;
    if (t == 0) g_is64 = is64;
    const int k0 = t * 4;
    if (k0 >= nnz) return;

    const int cnt = min(4, nnz - k0);
    int r[4];
    if (is64) {
        if (cnt == 4) {
            const int4 a = ((const int4*)rows32)[k0 / 2];
            const int4 b = ((const int4*)rows32)[k0 / 2 + 1];
            r[0] = a.x; r[1] = a.z; r[2] = b.x; r[3] = b.z;
        } else {
            for (int j = 0; j < cnt; j++) r[j] = rows32[2 * (k0 + j)];
        }
    } else {
        if (cnt == 4) {
            const int4 a = ((const int4*)rows32)[k0 / 4];
            r[0] = a.x; r[1] = a.y; r[2] = a.z; r[3] = a.w;
        } else {
            for (int j = 0; j < cnt; j++) r[j] = rows32[k0 + j];
        }
    }

    int rp = (k0 == 0) ? -1 : (is64 ? rows32[2 * (k0 - 1)] : rows32[k0 - 1]);
    for (int j = 0; j < cnt; j++) {
        const int rj = r[j];
        for (int x = rp + 1; x <= rj; x++) g_row_start[x] = k0 + j;
        rp = rj;
    }
    if (k0 + cnt == nnz) {
        for (int x = rp + 1; x <= n_rows; x++) g_row_start[x] = nnz;
    }
}

// ---------------------------------------------------------------------------
// Kernel 2: main SpMM — proven R2/R9/R11 inner loop in 2-warp CTAs.
// One WARP per output row; lane t owns output columns [4t, 4t+4) via float4.
// Stage 32 (val, byte-offset) pairs per warp in smem: the col index is
// pre-shifted to a byte offset (c << 9), so each gather address is
// per-lane-base + IADD instead of IMAD.WIDE — shorter LDS->LDG chain.
// Batches of 4 independent LDG.128 (16 L2 sectors in flight).
// ---------------------------------------------------------------------------
__global__ void __launch_bounds__(32 * WARPS_PER_BLOCK)
spmm_kernel(const float* __restrict__ values,
            const float* __restrict__ w,
            const int*   __restrict__ cols32,
            float*       __restrict__ out) {
    const int warp = threadIdx.x >> 5;
    const int lane = threadIdx.x & 31;
    const int r    = blockIdx.x * WARPS_PER_BLOCK + warp;
    const int is64 = g_is64;

    __shared__ float2 stage[WARPS_PER_BLOCK][32];

    const int lo = g_row_start[r];
    const int hi = g_row_start[r + 1];

    float4 acc = make_float4(0.f, 0.f, 0.f, 0.f);
    // Per-lane base: row stride is 512B; lane owns bytes [16*lane, 16*lane+16).
    const char* __restrict__ wb = (const char*)w + lane * 16;

    for (int base = lo; base < hi; base += 32) {
        const int m = min(32, hi - base);
        if (lane < m) {
            const int k = base + lane;
            const int c = is64 ? cols32[2 * k] : cols32[k];
            stage[warp][lane] = make_float2(values[k], __int_as_float(c << 9));
        }
        __syncwarp();

        int i = 0;
        #pragma unroll 1
        for (; i + 4 <= m; i += 4) {
            const float2 p0 = stage[warp][i + 0];
            const float2 p1 = stage[warp][i + 1];
            const float2 p2 = stage[warp][i + 2];
            const float2 p3 = stage[warp][i + 3];
            // 4 independent coalesced LDG.128s in flight
            const float4 w0 = *(const float4*)(wb + __float_as_int(p0.y));
            const float4 w1 = *(const float4*)(wb + __float_as_int(p1.y));
            const float4 w2 = *(const float4*)(wb + __float_as_int(p2.y));
            const float4 w3 = *(const float4*)(wb + __float_as_int(p3.y));
            acc.x = fmaf(p0.x, w0.x, acc.x); acc.y = fmaf(p0.x, w0.y, acc.y);
            acc.z = fmaf(p0.x, w0.z, acc.z); acc.w = fmaf(p0.x, w0.w, acc.w);
            acc.x = fmaf(p1.x, w1.x, acc.x); acc.y = fmaf(p1.x, w1.y, acc.y);
            acc.z = fmaf(p1.x, w1.z, acc.z); acc.w = fmaf(p1.x, w1.w, acc.w);
            acc.x = fmaf(p2.x, w2.x, acc.x); acc.y = fmaf(p2.x, w2.y, acc.y);
            acc.z = fmaf(p2.x, w2.z, acc.z); acc.w = fmaf(p2.x, w2.w, acc.w);
            acc.x = fmaf(p3.x, w3.x, acc.x); acc.y = fmaf(p3.x, w3.y, acc.y);
            acc.z = fmaf(p3.x, w3.z, acc.z); acc.w = fmaf(p3.x, w3.w, acc.w);
        }
        for (; i < m; i++) {
            const float2 p = stage[warp][i];
            const float4 wv = *(const float4*)(wb + __float_as_int(p.y));
            acc.x = fmaf(p.x, wv.x, acc.x); acc.y = fmaf(p.x, wv.y, acc.y);
            acc.z = fmaf(p.x, wv.z, acc.z); acc.w = fmaf(p.x, wv.w, acc.w);
        }
        __syncwarp();
    }

    ((float4*)out)[(size_t)r * 32 + lane] = acc;
}

// ---------------------------------------------------------------------------
// Launch
// Inputs (metadata order): values f32[NNZ], w f32[8192*128],
//                          rows int{32,64}[NNZ], cols int{32,64}[NNZ], n_rows
// ---------------------------------------------------------------------------
extern "C" void kernel_launch(void* const* d_in, const int* in_sizes, int n_in,
                              void* d_out, int out_size) {
    const float* values = (const float*)d_in[0];
    const float* w      = (const float*)d_in[1];
    const int*   rows32 = (const int*)d_in[2];
    const int*   cols32 = (const int*)d_in[3];
    float*       out    = (float*)d_out;

    const int nnz    = in_sizes[0];
    const int n_rows = out_size / OUT_UNITS;

    const int bs = 256;
    const int nthreads = (nnz + 3) / 4;
    build_offsets_kernel<<<(nthreads + bs - 1) / bs, bs>>>(rows32, nnz, n_rows);

    spmm_kernel<<<n_rows / WARPS_PER_BLOCK, 32 * WARPS_PER_BLOCK>>>(values, w, cols32, out);
}

// round 13
// speedup vs baseline: 1.1080x; 1.0018x over previous
#include <cuda_runtime.h>
#include <cuda_bf16.h>

#define OUT_UNITS 128
#define MAX_ROWS  16384
#define WARPS_PER_BLOCK 2

// ---------------------------------------------------------------------------
// Scratch (device globals — no allocation allowed in kernel_launch)
// ---------------------------------------------------------------------------
__device__ int g_is64;                       // 1 if rows/cols are int64, 0 if int32
__device__ int g_row_start[MAX_ROWS + 1];    // CSR-style row offsets

// ---------------------------------------------------------------------------
// Dtype probe: rows sorted ascending over [0, 16384). If int64 (LE), every odd
// 32-bit word is a zero high-half. If int32, odd words near n/4, n/2, 3n/4 are
// sorted row ids ~4096/8192/12288. Probed indices odd and < n: safe for both.
// ---------------------------------------------------------------------------
__device__ __forceinline__ int probe_is64(const int* __restrict__ rows32, int n) {
    int j1 = (n / 2) | 1;
    int j2 = (n / 4) | 1;
    int j3 = (int)(((long long)3 * n) / 4) | 1;
    int s = rows32[j1] | rows32[j2] | rows32[j3];
    return (s == 0) ? 1 : 0;
}

// ---------------------------------------------------------------------------
// Kernel 1: build row offsets from sorted COO rows (fused dtype detection).
// 4 elements per thread, vectorized int4 loads (R9-measured fastest variant).
// ---------------------------------------------------------------------------
__global__ void build_offsets_kernel(const int* __restrict__ rows32, int nnz, int n_rows) {
    const int is64 = probe_is64(rows32, nnz);

    const int t  = blockIdx.x * blockDim.x + threadIdx.x;
    if (t == 0) g_is64 = is64;
    const int k0 = t * 4;
    if (k0 >= nnz) return;

    const int cnt = min(4, nnz - k0);
    int r[4];
    if (is64) {
        if (cnt == 4) {
            const int4 a = ((const int4*)rows32)[k0 / 2];
            const int4 b = ((const int4*)rows32)[k0 / 2 + 1];
            r[0] = a.x; r[1] = a.z; r[2] = b.x; r[3] = b.z;
        } else {
            for (int j = 0; j < cnt; j++) r[j] = rows32[2 * (k0 + j)];
        }
    } else {
        if (cnt == 4) {
            const int4 a = ((const int4*)rows32)[k0 / 4];
            r[0] = a.x; r[1] = a.y; r[2] = a.z; r[3] = a.w;
        } else {
            for (int j = 0; j < cnt; j++) r[j] = rows32[k0 + j];
        }
    }

    int rp = (k0 == 0) ? -1 : (is64 ? rows32[2 * (k0 - 1)] : rows32[k0 - 1]);
    for (int j = 0; j < cnt; j++) {
        const int rj = r[j];
        for (int x = rp + 1; x <= rj; x++) g_row_start[x] = k0 + j;
        rp = rj;
    }
    if (k0 + cnt == nnz) {
        for (int x = rp + 1; x <= n_rows; x++) g_row_start[x] = nnz;
    }
}

// ---------------------------------------------------------------------------
// Kernel 2: main SpMM — measured-best inner loop (R11), 2-warp CTAs, with
// branch-free tail: staging pads lanes >= m with (v=0, c=0) and the gather
// loop runs to the next multiple of 4, so every batch is 4 independent
// LDG.128s (16 L2 sectors in flight) — no MLP=1 remainder. Dummy gathers hit
// the L1-hot row-0 line (v=0 contributes nothing).
// One WARP per output row; lane t owns output columns [4t, 4t+4) via float4.
// ---------------------------------------------------------------------------
__global__ void __launch_bounds__(32 * WARPS_PER_BLOCK)
spmm_kernel(const float* __restrict__ values,
            const float* __restrict__ w,
            const int*   __restrict__ cols32,
            float*       __restrict__ out) {
    const int warp = threadIdx.x >> 5;
    const int lane = threadIdx.x & 31;
    const int r    = blockIdx.x * WARPS_PER_BLOCK + warp;
    const int is64 = g_is64;

    __shared__ float2 stage[WARPS_PER_BLOCK][32];

    const int lo = g_row_start[r];
    const int hi = g_row_start[r + 1];

    float4 acc = make_float4(0.f, 0.f, 0.f, 0.f);
    const float4* __restrict__ w4 = (const float4*)w;   // w4[c*32 + lane]

    for (int base = lo; base < hi; base += 32) {
        const int m  = min(32, hi - base);
        const int mm = (m + 3) & ~3;                    // padded to multiple of 4

        // Branch-free staging: pad lanes >= m with (v=0, c=0).
        float v = 0.0f; int c = 0;
        const int k = base + lane;
        if (k < hi) {
            v = values[k];
            c = is64 ? cols32[2 * k] : cols32[k];
        }
        stage[warp][lane] = make_float2(v, __int_as_float(c));
        __syncwarp();

        #pragma unroll 1
        for (int i = 0; i < mm; i += 4) {
            const float2 p0 = stage[warp][i + 0];
            const float2 p1 = stage[warp][i + 1];
            const float2 p2 = stage[warp][i + 2];
            const float2 p3 = stage[warp][i + 3];
            // 4 independent coalesced LDG.128s in flight
            const float4 w0 = w4[(size_t)__float_as_int(p0.y) * 32 + lane];
            const float4 w1 = w4[(size_t)__float_as_int(p1.y) * 32 + lane];
            const float4 w2 = w4[(size_t)__float_as_int(p2.y) * 32 + lane];
            const float4 w3 = w4[(size_t)__float_as_int(p3.y) * 32 + lane];
            acc.x = fmaf(p0.x, w0.x, acc.x); acc.y = fmaf(p0.x, w0.y, acc.y);
            acc.z = fmaf(p0.x, w0.z, acc.z); acc.w = fmaf(p0.x, w0.w, acc.w);
            acc.x = fmaf(p1.x, w1.x, acc.x); acc.y = fmaf(p1.x, w1.y, acc.y);
            acc.z = fmaf(p1.x, w1.z, acc.z); acc.w = fmaf(p1.x, w1.w, acc.w);
            acc.x = fmaf(p2.x, w2.x, acc.x); acc.y = fmaf(p2.x, w2.y, acc.y);
            acc.z = fmaf(p2.x, w2.z, acc.z); acc.w = fmaf(p2.x, w2.w, acc.w);
            acc.x = fmaf(p3.x, w3.x, acc.x); acc.y = fmaf(p3.x, w3.y, acc.y);
            acc.z = fmaf(p3.x, w3.z, acc.z); acc.w = fmaf(p3.x, w3.w, acc.w);
        }
        __syncwarp();
    }

    ((float4*)out)[(size_t)r * 32 + lane] = acc;
}

// ---------------------------------------------------------------------------
// Launch
// Inputs (metadata order): values f32[NNZ], w f32[8192*128],
//                          rows int{32,64}[NNZ], cols int{32,64}[NNZ], n_rows
// ---------------------------------------------------------------------------
extern "C" void kernel_launch(void* const* d_in, const int* in_sizes, int n_in,
                              void* d_out, int out_size) {
    const float* values = (const float*)d_in[0];
    const float* w      = (const float*)d_in[1];
    const int*   rows32 = (const int*)d_in[2];
    const int*   cols32 = (const int*)d_in[3];
    float*       out    = (float*)d_out;

    const int nnz    = in_sizes[0];
    const int n_rows = out_size / OUT_UNITS;

    const int bs = 256;
    const int nthreads = (nnz + 3) / 4;
    build_offsets_kernel<<<(nthreads + bs - 1) / bs, bs>>>(rows32, nnz, n_rows);

    spmm_kernel<<<n_rows / WARPS_PER_BLOCK, 32 * WARPS_PER_BLOCK>>>(values, w, cols32, out);
}